// round 4
// baseline (speedup 1.0000x reference)
#include <cuda_runtime.h>

// RoPE, two-phase:
//  Phase 1: compact the block-diagonal rotation coefficients R[p,2k,2k:2k+2]
//           = (cos, -sin) into a dense 1MB table, one gather per unique (p,k).
//  Phase 2: pure streaming apply — coalesced table/x/out accesses.
//
// Inputs: x fp32 [2,2048,128], token_positions int32 [2,2048],
//         R fp32 [2048,128,128]. Output fp32 [2,2048,128].

#define MAX_POS   2048
#define NPAIR     64            // d_k/2
#define TBL_ELEMS (MAX_POS * NPAIR)

__device__ float2 g_ctable[TBL_ELEMS];   // [p][k] = (cos, -sin), 1 MB scratch

// Phase 1: one thread per (p, k). Single strided gather, coalesced store.
__global__ void __launch_bounds__(256)
rope_build_table(const float* __restrict__ R) {
    int idx = blockIdx.x * blockDim.x + threadIdx.x;
    if (idx >= TBL_ELEMS) return;
    int p = idx >> 6;
    int k = idx & 63;
    // (c, -s) adjacent at R[p, 2k, 2k] -> float offset p*16384 + k*258
    g_ctable[idx] = *reinterpret_cast<const float2*>(
        R + (size_t)p * 16384 + (size_t)k * 258);
}

// Phase 2: one warp per token, 2 pairs (4 floats) per lane. All coalesced.
__global__ void __launch_bounds__(256)
rope_apply(const float* __restrict__ x,
           const int* __restrict__ token_positions,
           float* __restrict__ out,
           int n_tokens) {
    int gtid  = blockIdx.x * blockDim.x + threadIdx.x;
    int token = gtid >> 5;
    int lane  = gtid & 31;
    if (token >= n_tokens) return;

    unsigned p = (unsigned)__ldg(&token_positions[token]);
    if (p >= (unsigned)MAX_POS) p = 0u;   // never fault on unexpected data

    // (c0, -s0, c1, -s1) for pairs 2*lane, 2*lane+1 — contiguous 16B
    const float4 cs = *reinterpret_cast<const float4*>(
        g_ctable + (size_t)p * NPAIR + (size_t)lane * 2);

    const float* xt = x + (size_t)token * 128 + (size_t)lane * 4;
    const float4 xv = *reinterpret_cast<const float4*>(xt);

    float4 o;
    o.x = cs.x * xv.x + cs.y * xv.y;   // c0*x0 - s0*x1
    o.y = cs.x * xv.y - cs.y * xv.x;   // s0*x0 + c0*x1
    o.z = cs.z * xv.z + cs.w * xv.w;   // c1*x2 - s1*x3
    o.w = cs.z * xv.w - cs.w * xv.z;   // s1*x2 + c1*x3

    *reinterpret_cast<float4*>(out + (size_t)token * 128 + (size_t)lane * 4) = o;
}

extern "C" void kernel_launch(void* const* d_in, const int* in_sizes, int n_in,
                              void* d_out, int out_size) {
    const float* x   = (const float*)d_in[0];
    const int*   pos = (const int*)d_in[1];
    const float* R   = (const float*)d_in[2];
    float*       out = (float*)d_out;

    // Phase 1: 131072 threads
    rope_build_table<<<TBL_ELEMS / 256, 256>>>(R);

    // Phase 2: one warp per token
    const int n_tokens = out_size / 128;
    const int threads  = 256;
    const int blocks   = (n_tokens * 32 + threads - 1) / threads;
    rope_apply<<<blocks, threads>>>(x, pos, out, n_tokens);
}

// round 5
// speedup vs baseline: 1.0037x; 1.0037x over previous
#include <cuda_runtime.h>

// RoPE, single kernel, token-major warp layout.
// Inputs: x fp32 [2,2048,128], token_positions int32 [2,2048],
//         R fp32 [2048,128,128]. Output fp32 [2,2048,128].
//
// grid = (n_tokens/256, 64): blockIdx.y = rotation-pair index k (0..63),
// threads cover 256 consecutive tokens. Warp = 32 consecutive tokens at one k:
//  - pos read is one coalesced line per warp,
//  - positions are sorted, so warp R-gather addresses sit in one ~2MB page
//    and duplicate positions merge into a single request,
//  - (c,-s) adjacent at R[p, 2k, 2k] -> exact reference coefficients.
// __ldcs/__stcs: streaming, evict-first, avoid wide L2 promotion on gathers.

__global__ void __launch_bounds__(256)
rope_tmajor_kernel(const float* __restrict__ x,
                   const int* __restrict__ token_positions,
                   const float* __restrict__ R,
                   float* __restrict__ out) {
    const int token = blockIdx.x * blockDim.x + threadIdx.x; // 32 consecutive per warp
    const int k     = blockIdx.y;                            // pair index 0..63

    unsigned p = (unsigned)__ldg(&token_positions[token]);
    if (p >= 2048u) p = 0u;   // never fault on unexpected data

    // (c, -s) at R[p, 2k, 2k..2k+1]: float offset p*16384 + k*258
    const float2 cms = __ldcs(reinterpret_cast<const float2*>(
        R + (size_t)p * 16384 + (size_t)k * 258));

    const float2 xv = __ldcs(reinterpret_cast<const float2*>(
        x + (size_t)token * 128 + (size_t)k * 2));

    float2 o;
    o.x = cms.x * xv.x + cms.y * xv.y;   // c*x0 - s*x1
    o.y = cms.x * xv.y - cms.y * xv.x;   // s*x0 + c*x1

    __stcs(reinterpret_cast<float2*>(out + (size_t)token * 128 + (size_t)k * 2), o);
}

extern "C" void kernel_launch(void* const* d_in, const int* in_sizes, int n_in,
                              void* d_out, int out_size) {
    const float* x   = (const float*)d_in[0];
    const int*   pos = (const int*)d_in[1];
    const float* R   = (const float*)d_in[2];
    float*       out = (float*)d_out;

    const int n_tokens = out_size / 128;          // 4096
    dim3 block(256);
    dim3 grid((n_tokens + 255) / 256, 64);        // (16, 64) = 1024 CTAs
    rope_tmajor_kernel<<<grid, block>>>(x, pos, R, out);
}